// round 16
// baseline (speedup 1.0000x reference)
#include <cuda_runtime.h>
#include <math.h>

#define T_LEN 1024
#define NN    1022            /* templates */
#define PAD   1104
#define RR    0.2f
#define NTHR  128
#define NSLICE 8
#define NBLK  (128 * NSLICE)

typedef unsigned long long u64;

__device__ unsigned int g_cm[128];
__device__ unsigned int g_cm1[128];
__device__ unsigned int g_barrier;

__device__ __forceinline__ u64 fma2(u64 a, u64 b, u64 c) {
    u64 r;
    asm("fma.rn.f32x2 %0, %1, %2, %3;" : "=l"(r) : "l"(a), "l"(b), "l"(c));
    return r;
}
__device__ __forceinline__ unsigned int lo32(u64 v) { return (unsigned int)v; }
__device__ __forceinline__ unsigned int hi32(u64 v) { return (unsigned int)(v >> 32); }

#define FMA2SH(acc, W, A)                                            \
    do {                                                             \
        u64 _d = fma2((W), NEG1, (A));                               \
        u64 _u = fma2(_d, _d, NRS2);                                 \
        (acc) = __funnelshift_l(lo32(_u), (acc), 1);                 \
        (acc) = __funnelshift_l(hi32(_u), (acc), 1);                 \
    } while (0)

// ---- single self-contained unit (tail), software-pipelined loads ----
__device__ __forceinline__ void unit_count(const float* __restrict__ xs,
                                           const float* __restrict__ ys,
                                           int k0, int dbase, int remBase,
                                           float Rs2, u64 NEG1, u64 NRS2,
                                           unsigned int& cm, unsigned int& cm1) {
    const int B = k0 + dbase - 1;                     // ≡ 0 mod 4
    const ulonglong2* __restrict__ Ap = reinterpret_cast<const ulonglong2*>(xs + k0);
    const ulonglong2* __restrict__ Ep = reinterpret_cast<const ulonglong2*>(xs + B);
    const ulonglong2* __restrict__ Yp = reinterpret_cast<const ulonglong2*>(ys + B);
    unsigned int acc0 = 0, acc1 = 0, acc2 = 0, acc3 = 0;
    u64 e1 = Ep[0].y;
    ulonglong2 Y0 = Yp[0];
    ulonglong2 Ac = Ap[0];
    ulonglong2 Ec = Ep[1];
    ulonglong2 Yc = Yp[1];
    #pragma unroll
    for (int q = 0; q < 8; q++) {
        ulonglong2 An = Ap[q + 1];
        ulonglong2 En = Ep[q + 2];
        ulonglong2 Yn = Yp[q + 2];
        FMA2SH(acc0, Y0.x, Ac.x);  FMA2SH(acc0, Y0.y, Ac.y);   // s=0
        FMA2SH(acc1, e1,   Ac.x);  FMA2SH(acc1, Ec.x, Ac.y);   // s=1
        FMA2SH(acc2, Y0.y, Ac.x);  FMA2SH(acc2, Yc.x, Ac.y);   // s=2
        FMA2SH(acc3, Ec.x, Ac.x);  FMA2SH(acc3, Ec.y, Ac.y);   // s=3
        e1 = Ec.y; Y0 = Yc;
        Ac = An; Ec = En; Yc = Yn;
    }
    const float a32 = xs[k0 + 32];
    const float a33 = xs[k0 + 33];
    unsigned int acc[4] = {acc0, acc1, acc2, acc3};
    #pragma unroll
    for (int s = 0; s < 4; s++) {
        float W33 = xs[B + 33 + s];
        float W34 = xs[B + 34 + s];
        float d32 = a32 - W33;
        float d33 = a33 - W34;
        float u32 = fmaf(d32, d32, -Rs2);
        float u33 = fmaf(d33, d33, -Rs2);
        unsigned int ext = (__float_as_uint(u32) & 0x80000000u)
                         | ((__float_as_uint(u33) >> 1) & 0x40000000u);
        int rem = remBase - s;
        unsigned int mask = (rem >= 32) ? 0xffffffffu
                          : ((rem <= 0) ? 0u : (0xffffffffu << (32 - rem)));
        unsigned int S1 = __funnelshift_l(ext, acc[s], 1);
        unsigned int S2 = __funnelshift_l(ext, acc[s], 2);
        unsigned int mm = acc[s] & S1 & mask;
        cm  += __popc(mm);
        cm1 += __popc(mm & S2);
    }
}

// ---- two interleaved independent units (ILP x2), software-pipelined ----
__device__ __forceinline__ void unit2_count(const float* __restrict__ xs,
                                            const float* __restrict__ ys,
                                            int k0a, int dba, int remA,
                                            int k0b, int dbb, int remB,
                                            float Rs2, u64 NEG1, u64 NRS2,
                                            unsigned int& cm, unsigned int& cm1) {
    const int BA = k0a + dba - 1;
    const int BB = k0b + dbb - 1;
    const ulonglong2* __restrict__ ApA = reinterpret_cast<const ulonglong2*>(xs + k0a);
    const ulonglong2* __restrict__ EpA = reinterpret_cast<const ulonglong2*>(xs + BA);
    const ulonglong2* __restrict__ YpA = reinterpret_cast<const ulonglong2*>(ys + BA);
    const ulonglong2* __restrict__ ApB = reinterpret_cast<const ulonglong2*>(xs + k0b);
    const ulonglong2* __restrict__ EpB = reinterpret_cast<const ulonglong2*>(xs + BB);
    const ulonglong2* __restrict__ YpB = reinterpret_cast<const ulonglong2*>(ys + BB);
    unsigned int aA0 = 0, aA1 = 0, aA2 = 0, aA3 = 0;
    unsigned int aB0 = 0, aB1 = 0, aB2 = 0, aB3 = 0;
    u64 e1A = EpA[0].y;
    u64 e1B = EpB[0].y;
    ulonglong2 Y0A = YpA[0];
    ulonglong2 Y0B = YpB[0];
    ulonglong2 AcA = ApA[0], EcA = EpA[1], YcA = YpA[1];
    ulonglong2 AcB = ApB[0], EcB = EpB[1], YcB = YpB[1];
    #pragma unroll
    for (int q = 0; q < 8; q++) {
        ulonglong2 AnA = ApA[q + 1];
        ulonglong2 EnA = EpA[q + 2];
        ulonglong2 YnA = YpA[q + 2];
        ulonglong2 AnB = ApB[q + 1];
        ulonglong2 EnB = EpB[q + 2];
        ulonglong2 YnB = YpB[q + 2];
        FMA2SH(aA0, Y0A.x, AcA.x);  FMA2SH(aB0, Y0B.x, AcB.x);
        FMA2SH(aA0, Y0A.y, AcA.y);  FMA2SH(aB0, Y0B.y, AcB.y);
        FMA2SH(aA1, e1A,   AcA.x);  FMA2SH(aB1, e1B,   AcB.x);
        FMA2SH(aA1, EcA.x, AcA.y);  FMA2SH(aB1, EcB.x, AcB.y);
        FMA2SH(aA2, Y0A.y, AcA.x);  FMA2SH(aB2, Y0B.y, AcB.x);
        FMA2SH(aA2, YcA.x, AcA.y);  FMA2SH(aB2, YcB.x, AcB.y);
        FMA2SH(aA3, EcA.x, AcA.x);  FMA2SH(aB3, EcB.x, AcB.x);
        FMA2SH(aA3, EcA.y, AcA.y);  FMA2SH(aB3, EcB.y, AcB.y);
        e1A = EcA.y; Y0A = YcA;
        e1B = EcB.y; Y0B = YcB;
        AcA = AnA; EcA = EnA; YcA = YnA;
        AcB = AnB; EcB = EnB; YcB = YnB;
    }
    {
        const float a32 = xs[k0a + 32];
        const float a33 = xs[k0a + 33];
        unsigned int acc[4] = {aA0, aA1, aA2, aA3};
        #pragma unroll
        for (int s = 0; s < 4; s++) {
            float W33 = xs[BA + 33 + s];
            float W34 = xs[BA + 34 + s];
            float d32 = a32 - W33;
            float d33 = a33 - W34;
            float u32 = fmaf(d32, d32, -Rs2);
            float u33 = fmaf(d33, d33, -Rs2);
            unsigned int ext = (__float_as_uint(u32) & 0x80000000u)
                             | ((__float_as_uint(u33) >> 1) & 0x40000000u);
            int rem = remA - s;
            unsigned int mask = (rem >= 32) ? 0xffffffffu
                              : ((rem <= 0) ? 0u : (0xffffffffu << (32 - rem)));
            unsigned int S1 = __funnelshift_l(ext, acc[s], 1);
            unsigned int S2 = __funnelshift_l(ext, acc[s], 2);
            unsigned int mm = acc[s] & S1 & mask;
            cm  += __popc(mm);
            cm1 += __popc(mm & S2);
        }
    }
    {
        const float a32 = xs[k0b + 32];
        const float a33 = xs[k0b + 33];
        unsigned int acc[4] = {aB0, aB1, aB2, aB3};
        #pragma unroll
        for (int s = 0; s < 4; s++) {
            float W33 = xs[BB + 33 + s];
            float W34 = xs[BB + 34 + s];
            float d32 = a32 - W33;
            float d33 = a33 - W34;
            float u32 = fmaf(d32, d32, -Rs2);
            float u33 = fmaf(d33, d33, -Rs2);
            unsigned int ext = (__float_as_uint(u32) & 0x80000000u)
                             | ((__float_as_uint(u33) >> 1) & 0x40000000u);
            int rem = remB - s;
            unsigned int mask = (rem >= 32) ? 0xffffffffu
                              : ((rem <= 0) ? 0u : (0xffffffffu << (32 - rem)));
            unsigned int S1 = __funnelshift_l(ext, acc[s], 1);
            unsigned int S2 = __funnelshift_l(ext, acc[s], 2);
            unsigned int mm = acc[s] & S1 & mask;
            cm  += __popc(mm);
            cm1 += __popc(mm & S2);
        }
    }
}

__global__ __launch_bounds__(NTHR, 4)
void sampen_kernel(const float* __restrict__ pred, const float* __restrict__ tgt,
                   float* __restrict__ out) {
    __shared__ __align__(16) float xs[PAD];
    __shared__ __align__(16) float ys[PAD];     // ys[i] = xs[i+1]
    __shared__ double redA[4], redB[4];
    __shared__ unsigned int redc[4], redc1[4];
    __shared__ float s_thresh2;
    __shared__ unsigned int s_last;
    __shared__ float ent_sm[128];
    __shared__ float part_sm[2];

    const int tid   = threadIdx.x;
    const int sig   = blockIdx.x & 127;
    const int slice = blockIdx.x >> 7;          // 0..7
    const float* src = (sig < 64) ? (pred + (size_t)sig * T_LEN)
                                  : (tgt  + (size_t)(sig - 64) * T_LEN);

    // ---- prologue: stage signal (8 floats/thread via float4) + zero pad ----
    float4 f0 = reinterpret_cast<const float4*>(src)[tid];
    float4 f1 = reinterpret_cast<const float4*>(src)[tid + 128];
    reinterpret_cast<float4*>(xs)[tid]       = f0;
    reinterpret_cast<float4*>(xs)[tid + 128] = f1;
    if (tid < PAD - T_LEN) xs[T_LEN + tid] = 0.0f;   // 80 pad floats

    // fp64 std (ddof=1); mean cancels inside |xi-xj| -> Rs2 = (R*(std+eps))^2
    double ls  = (double)f0.x + (double)f0.y + (double)f0.z + (double)f0.w
               + (double)f1.x + (double)f1.y + (double)f1.z + (double)f1.w;
    double ls2 = (double)f0.x * f0.x + (double)f0.y * f0.y
               + (double)f0.z * f0.z + (double)f0.w * f0.w
               + (double)f1.x * f1.x + (double)f1.y * f1.y
               + (double)f1.z * f1.z + (double)f1.w * f1.w;
    #pragma unroll
    for (int o = 16; o > 0; o >>= 1) {
        ls  += __shfl_down_sync(0xffffffffu, ls,  o);
        ls2 += __shfl_down_sync(0xffffffffu, ls2, o);
    }
    if ((tid & 31) == 0) { redA[tid >> 5] = ls; redB[tid >> 5] = ls2; }
    __syncthreads();
    // shifted copy (xs visible now)
    #pragma unroll
    for (int i = tid; i < PAD - 1; i += NTHR) ys[i] = xs[i + 1];
    if (tid == 0) {
        ys[PAD - 1] = 0.0f;
        double S = redA[0] + redA[1] + redA[2] + redA[3];
        double S2 = redB[0] + redB[1] + redB[2] + redB[3];
        double var = (S2 - S * S / (double)T_LEN) / (double)(T_LEN - 1);
        double sd  = sqrt(var);
        double rs  = (double)RR * (sd + 1e-8);
        s_thresh2  = (float)(rs * rs);
    }
    __syncthreads();
    const float Rs2 = s_thresh2;
    const u64 NEG1 = 0xBF800000BF800000ull;
    const unsigned int nr = __float_as_uint(-Rs2);
    const u64 NRS2 = (u64)nr | ((u64)nr << 32);

    // ---- counting: P = tid owns pair (P, 255-P) = 33 units; this block does
    // units [g0,g1) of that list (slice sizes {4,...,4,5}); uniform per block ----
    const int P  = tid;
    const int dA = 4 * P + 1;
    const int LA = NN - dA;
    const int dB = 1021 - 4 * P;
    const int LB = NN - dB;
    const int CA = (LA + 31) >> 5;
    const int g0 = (slice * 33) >> 3;
    const int g1 = ((slice + 1) * 33) >> 3;

    unsigned int cm = 0, cm1 = 0;
    int j = g0;
    #pragma unroll 1
    for (; j + 1 < g1; j += 2) {
        bool inA0  = (j < CA);
        int dbase0 = inA0 ? dA : dB;
        int c0     = inA0 ? j  : j - CA;
        int Lb0    = inA0 ? LA : LB;
        int jb     = j + 1;
        bool inA1  = (jb < CA);
        int dbase1 = inA1 ? dA : dB;
        int c1     = inA1 ? jb : jb - CA;
        int Lb1    = inA1 ? LA : LB;
        unit2_count(xs, ys, c0 << 5, dbase0, Lb0 - (c0 << 5),
                            c1 << 5, dbase1, Lb1 - (c1 << 5),
                    Rs2, NEG1, NRS2, cm, cm1);
    }
    if (j < g1) {                       // only slice 7 (uniform per block)
        bool inA  = (j < CA);
        int dbase = inA ? dA : dB;
        int c     = inA ? j  : j - CA;
        int Lb    = inA ? LA : LB;
        unit_count(xs, ys, c << 5, dbase, Lb - (c << 5), Rs2, NEG1, NRS2, cm, cm1);
    }

    // ---- block-reduce counts, then global integer accumulate ----
    #pragma unroll
    for (int o = 16; o > 0; o >>= 1) {
        cm  += __shfl_down_sync(0xffffffffu, cm,  o);
        cm1 += __shfl_down_sync(0xffffffffu, cm1, o);
    }
    if ((tid & 31) == 0) { redc[tid >> 5] = cm; redc1[tid >> 5] = cm1; }
    __syncthreads();
    if (tid == 0) {
        unsigned int tm  = redc[0] + redc[1] + redc[2] + redc[3];
        unsigned int tm1 = redc1[0] + redc1[1] + redc1[2] + redc1[3];
        atomicAdd(&g_cm[sig], tm);
        atomicAdd(&g_cm1[sig], tm1);
        __threadfence();
        s_last = (atomicAdd(&g_barrier, 1) == (unsigned int)(NBLK - 1)) ? 1u : 0u;
    }
    __syncthreads();

    // ---- last block: entropies + MSE + counter reset (graph-replay safe) ----
    if (s_last) {
        __threadfence();
        unsigned int um  = __ldcg(&g_cm[tid]);
        unsigned int um1 = __ldcg(&g_cm1[tid]);
        // symmetric matrix + zero diagonal: matches = NN + 2*upper
        unsigned int matches_m  = (unsigned int)NN + 2u * um;
        unsigned int matches_m1 = (unsigned int)NN + 2u * um1;
        float ratio = (float)matches_m1 / (float)matches_m;   // > 0 always
        ratio = fmaxf(ratio, 1e-30f);
        ent_sm[tid] = -logf(ratio);
        // reset for next replay
        g_cm[tid]  = 0;
        g_cm1[tid] = 0;
        __syncthreads();
        if (tid < 64) {
            float d = ent_sm[tid] - ent_sm[64 + tid];
            float v = d * d;
            #pragma unroll
            for (int o = 16; o > 0; o >>= 1)
                v += __shfl_down_sync(0xffffffffu, v, o);
            if ((tid & 31) == 0) part_sm[tid >> 5] = v;
        }
        __syncthreads();
        if (tid == 0) {
            out[0] = (part_sm[0] + part_sm[1]) * (1.0f / 64.0f);
            g_barrier = 0;
        }
    }
}

extern "C" void kernel_launch(void* const* d_in, const int* in_sizes, int n_in,
                              void* d_out, int out_size) {
    const float* pred = (const float*)d_in[0];
    const float* tgt  = (const float*)d_in[1];
    float* out = (float*)d_out;
    sampen_kernel<<<NBLK, NTHR>>>(pred, tgt, out);
}

// round 17
// speedup vs baseline: 1.0860x; 1.0860x over previous
#include <cuda_runtime.h>
#include <math.h>

#define T_LEN 1024
#define NN    1022            /* templates */
#define PAD   1104
#define RR    0.2f
#define NTHR  384
#define NWARP (NTHR / 32)
#define GRID  148
#define LTOT  (128 * 33)      /* 4224 global unit-layers */

typedef unsigned long long u64;

__device__ unsigned int g_cm[128];
__device__ unsigned int g_cm1[128];
__device__ unsigned int g_barrier;

__device__ __forceinline__ u64 fma2(u64 a, u64 b, u64 c) {
    u64 r;
    asm("fma.rn.f32x2 %0, %1, %2, %3;" : "=l"(r) : "l"(a), "l"(b), "l"(c));
    return r;
}
__device__ __forceinline__ unsigned int lo32(u64 v) { return (unsigned int)v; }
__device__ __forceinline__ unsigned int hi32(u64 v) { return (unsigned int)(v >> 32); }

#define FMA2SH(acc, W, A)                                            \
    do {                                                             \
        u64 _d = fma2((W), NEG1, (A));                               \
        u64 _u = fma2(_d, _d, NRS2);                                 \
        (acc) = __funnelshift_l(lo32(_u), (acc), 1);                 \
        (acc) = __funnelshift_l(hi32(_u), (acc), 1);                 \
    } while (0)

// ---- single unit, software-pipelined (as R15) ----
__device__ __forceinline__ void unit_count(const float* __restrict__ xs,
                                           const float* __restrict__ ys,
                                           int k0, int dbase, int remBase,
                                           float Rs2, u64 NEG1, u64 NRS2,
                                           unsigned int& cm, unsigned int& cm1) {
    const int B = k0 + dbase - 1;
    const ulonglong2* __restrict__ Ap = reinterpret_cast<const ulonglong2*>(xs + k0);
    const ulonglong2* __restrict__ Ep = reinterpret_cast<const ulonglong2*>(xs + B);
    const ulonglong2* __restrict__ Yp = reinterpret_cast<const ulonglong2*>(ys + B);
    unsigned int acc0 = 0, acc1 = 0, acc2 = 0, acc3 = 0;
    u64 e1 = Ep[0].y;
    ulonglong2 Y0 = Yp[0];
    ulonglong2 Ac = Ap[0];
    ulonglong2 Ec = Ep[1];
    ulonglong2 Yc = Yp[1];
    #pragma unroll
    for (int q = 0; q < 8; q++) {
        ulonglong2 An = Ap[q + 1];
        ulonglong2 En = Ep[q + 2];
        ulonglong2 Yn = Yp[q + 2];
        FMA2SH(acc0, Y0.x, Ac.x);  FMA2SH(acc0, Y0.y, Ac.y);
        FMA2SH(acc1, e1,   Ac.x);  FMA2SH(acc1, Ec.x, Ac.y);
        FMA2SH(acc2, Y0.y, Ac.x);  FMA2SH(acc2, Yc.x, Ac.y);
        FMA2SH(acc3, Ec.x, Ac.x);  FMA2SH(acc3, Ec.y, Ac.y);
        e1 = Ec.y; Y0 = Yc;
        Ac = An; Ec = En; Yc = Yn;
    }
    const float a32 = xs[k0 + 32];
    const float a33 = xs[k0 + 33];
    unsigned int acc[4] = {acc0, acc1, acc2, acc3};
    #pragma unroll
    for (int s = 0; s < 4; s++) {
        float W33 = xs[B + 33 + s];
        float W34 = xs[B + 34 + s];
        float d32 = a32 - W33;
        float d33 = a33 - W34;
        float u32 = fmaf(d32, d32, -Rs2);
        float u33 = fmaf(d33, d33, -Rs2);
        unsigned int ext = (__float_as_uint(u32) & 0x80000000u)
                         | ((__float_as_uint(u33) >> 1) & 0x40000000u);
        int rem = remBase - s;
        unsigned int mask = (rem >= 32) ? 0xffffffffu
                          : ((rem <= 0) ? 0u : (0xffffffffu << (32 - rem)));
        unsigned int S1 = __funnelshift_l(ext, acc[s], 1);
        unsigned int S2 = __funnelshift_l(ext, acc[s], 2);
        unsigned int mm = acc[s] & S1 & mask;
        cm  += __popc(mm);
        cm1 += __popc(mm & S2);
    }
}

// ---- two interleaved units (ILP x2), software-pipelined (as R15) ----
__device__ __forceinline__ void unit2_count(const float* __restrict__ xs,
                                            const float* __restrict__ ys,
                                            int k0a, int dba, int remA,
                                            int k0b, int dbb, int remB,
                                            float Rs2, u64 NEG1, u64 NRS2,
                                            unsigned int& cm, unsigned int& cm1) {
    const int BA = k0a + dba - 1;
    const int BB = k0b + dbb - 1;
    const ulonglong2* __restrict__ ApA = reinterpret_cast<const ulonglong2*>(xs + k0a);
    const ulonglong2* __restrict__ EpA = reinterpret_cast<const ulonglong2*>(xs + BA);
    const ulonglong2* __restrict__ YpA = reinterpret_cast<const ulonglong2*>(ys + BA);
    const ulonglong2* __restrict__ ApB = reinterpret_cast<const ulonglong2*>(xs + k0b);
    const ulonglong2* __restrict__ EpB = reinterpret_cast<const ulonglong2*>(xs + BB);
    const ulonglong2* __restrict__ YpB = reinterpret_cast<const ulonglong2*>(ys + BB);
    unsigned int aA0 = 0, aA1 = 0, aA2 = 0, aA3 = 0;
    unsigned int aB0 = 0, aB1 = 0, aB2 = 0, aB3 = 0;
    u64 e1A = EpA[0].y;
    u64 e1B = EpB[0].y;
    ulonglong2 Y0A = YpA[0];
    ulonglong2 Y0B = YpB[0];
    ulonglong2 AcA = ApA[0], EcA = EpA[1], YcA = YpA[1];
    ulonglong2 AcB = ApB[0], EcB = EpB[1], YcB = YpB[1];
    #pragma unroll
    for (int q = 0; q < 8; q++) {
        ulonglong2 AnA = ApA[q + 1];
        ulonglong2 EnA = EpA[q + 2];
        ulonglong2 YnA = YpA[q + 2];
        ulonglong2 AnB = ApB[q + 1];
        ulonglong2 EnB = EpB[q + 2];
        ulonglong2 YnB = YpB[q + 2];
        FMA2SH(aA0, Y0A.x, AcA.x);  FMA2SH(aB0, Y0B.x, AcB.x);
        FMA2SH(aA0, Y0A.y, AcA.y);  FMA2SH(aB0, Y0B.y, AcB.y);
        FMA2SH(aA1, e1A,   AcA.x);  FMA2SH(aB1, e1B,   AcB.x);
        FMA2SH(aA1, EcA.x, AcA.y);  FMA2SH(aB1, EcB.x, AcB.y);
        FMA2SH(aA2, Y0A.y, AcA.x);  FMA2SH(aB2, Y0B.y, AcB.x);
        FMA2SH(aA2, YcA.x, AcA.y);  FMA2SH(aB2, YcB.x, AcB.y);
        FMA2SH(aA3, EcA.x, AcA.x);  FMA2SH(aB3, EcB.x, AcB.x);
        FMA2SH(aA3, EcA.y, AcA.y);  FMA2SH(aB3, EcB.y, AcB.y);
        e1A = EcA.y; Y0A = YcA;
        e1B = EcB.y; Y0B = YcB;
        AcA = AnA; EcA = EnA; YcA = YnA;
        AcB = AnB; EcB = EnB; YcB = YnB;
    }
    {
        const float a32 = xs[k0a + 32];
        const float a33 = xs[k0a + 33];
        unsigned int acc[4] = {aA0, aA1, aA2, aA3};
        #pragma unroll
        for (int s = 0; s < 4; s++) {
            float W33 = xs[BA + 33 + s];
            float W34 = xs[BA + 34 + s];
            float d32 = a32 - W33;
            float d33 = a33 - W34;
            float u32 = fmaf(d32, d32, -Rs2);
            float u33 = fmaf(d33, d33, -Rs2);
            unsigned int ext = (__float_as_uint(u32) & 0x80000000u)
                             | ((__float_as_uint(u33) >> 1) & 0x40000000u);
            int rem = remA - s;
            unsigned int mask = (rem >= 32) ? 0xffffffffu
                              : ((rem <= 0) ? 0u : (0xffffffffu << (32 - rem)));
            unsigned int S1 = __funnelshift_l(ext, acc[s], 1);
            unsigned int S2 = __funnelshift_l(ext, acc[s], 2);
            unsigned int mm = acc[s] & S1 & mask;
            cm  += __popc(mm);
            cm1 += __popc(mm & S2);
        }
    }
    {
        const float a32 = xs[k0b + 32];
        const float a33 = xs[k0b + 33];
        unsigned int acc[4] = {aB0, aB1, aB2, aB3};
        #pragma unroll
        for (int s = 0; s < 4; s++) {
            float W33 = xs[BB + 33 + s];
            float W34 = xs[BB + 34 + s];
            float d32 = a32 - W33;
            float d33 = a33 - W34;
            float u32 = fmaf(d32, d32, -Rs2);
            float u33 = fmaf(d33, d33, -Rs2);
            unsigned int ext = (__float_as_uint(u32) & 0x80000000u)
                             | ((__float_as_uint(u33) >> 1) & 0x40000000u);
            int rem = remB - s;
            unsigned int mask = (rem >= 32) ? 0xffffffffu
                              : ((rem <= 0) ? 0u : (0xffffffffu << (32 - rem)));
            unsigned int S1 = __funnelshift_l(ext, acc[s], 1);
            unsigned int S2 = __funnelshift_l(ext, acc[s], 2);
            unsigned int mm = acc[s] & S1 & mask;
            cm  += __popc(mm);
            cm1 += __popc(mm & S2);
        }
    }
}

// process this thread's layers (l ≡ start pattern mod 3) in [l, lend) of one
// signal segment; jofs = 33 * signal_index. Warp-uniform trip counts.
__device__ __forceinline__ void seg_process(const float* __restrict__ xs,
                                            const float* __restrict__ ys,
                                            int l, int lend, int jofs,
                                            int dA, int dB, int LA, int LB, int CA,
                                            float Rs2, u64 NEG1, u64 NRS2,
                                            unsigned int& cm, unsigned int& cm1) {
    #pragma unroll 1
    while (l + 3 < lend) {
        int j0 = l - jofs;
        int j1 = j0 + 3;
        bool a0 = (j0 < CA);
        int db0 = a0 ? dA : dB;
        int c0  = a0 ? j0 : j0 - CA;
        int Lb0 = a0 ? LA : LB;
        bool a1 = (j1 < CA);
        int db1 = a1 ? dA : dB;
        int c1  = a1 ? j1 : j1 - CA;
        int Lb1 = a1 ? LA : LB;
        unit2_count(xs, ys, c0 << 5, db0, Lb0 - (c0 << 5),
                            c1 << 5, db1, Lb1 - (c1 << 5),
                    Rs2, NEG1, NRS2, cm, cm1);
        l += 6;
    }
    if (l < lend) {
        int j = l - jofs;
        bool a = (j < CA);
        int db = a ? dA : dB;
        int c  = a ? j : j - CA;
        int Lb = a ? LA : LB;
        unit_count(xs, ys, c << 5, db, Lb - (c << 5), Rs2, NEG1, NRS2, cm, cm1);
    }
}

__global__ __launch_bounds__(NTHR, 1)
void sampen_kernel(const float* __restrict__ pred, const float* __restrict__ tgt,
                   float* __restrict__ out) {
    __shared__ __align__(16) float xs0[PAD], ys0[PAD];
    __shared__ __align__(16) float xs1[PAD], ys1[PAD];
    __shared__ double rA[NWARP], rB[NWARP], rC[NWARP], rD[NWARP];
    __shared__ unsigned int redc[4][NWARP];
    __shared__ float s_thr0, s_thr1;
    __shared__ unsigned int s_last;
    __shared__ float ent_sm[128];
    __shared__ float part_sm[2];

    const int tid = threadIdx.x;
    const int b   = blockIdx.x;
    const int B0  = (b * LTOT) / GRID;
    const int B1  = ((b + 1) * LTOT) / GRID;
    const int sg0 = B0 / 33;                 // first signal
    const int sg1 = (B1 - 1) / 33;           // last signal (sg1 <= sg0 + 1)

    const float* srcA = (sg0 < 64) ? (pred + (size_t)sg0 * T_LEN)
                                   : (tgt  + (size_t)(sg0 - 64) * T_LEN);
    const float* srcB = (sg1 < 64) ? (pred + (size_t)sg1 * T_LEN)
                                   : (tgt  + (size_t)(sg1 - 64) * T_LEN);

    // ---- stage both signals + zero pad ----
    float p0 = srcA[tid];
    float p1 = srcA[tid + NTHR];
    float p2 = (tid + 2 * NTHR < T_LEN) ? srcA[tid + 2 * NTHR] : 0.0f;
    xs0[tid]        = p0;
    xs0[tid + NTHR] = p1;
    if (tid + 2 * NTHR < T_LEN) xs0[tid + 2 * NTHR] = p2;
    float q0 = srcB[tid];
    float q1 = srcB[tid + NTHR];
    float q2 = (tid + 2 * NTHR < T_LEN) ? srcB[tid + 2 * NTHR] : 0.0f;
    xs1[tid]        = q0;
    xs1[tid + NTHR] = q1;
    if (tid + 2 * NTHR < T_LEN) xs1[tid + 2 * NTHR] = q2;
    for (int i = T_LEN + tid; i < PAD; i += NTHR) { xs0[i] = 0.0f; xs1[i] = 0.0f; }

    // ---- fp64 std (ddof=1) for BOTH signals -> Rs2 = (R*(std+eps))^2 ----
    double lsA  = (double)p0 + (double)p1 + (double)p2;
    double ls2A = (double)p0 * p0 + (double)p1 * p1 + (double)p2 * p2;
    double lsB  = (double)q0 + (double)q1 + (double)q2;
    double ls2B = (double)q0 * q0 + (double)q1 * q1 + (double)q2 * q2;
    #pragma unroll
    for (int o = 16; o > 0; o >>= 1) {
        lsA  += __shfl_down_sync(0xffffffffu, lsA,  o);
        ls2A += __shfl_down_sync(0xffffffffu, ls2A, o);
        lsB  += __shfl_down_sync(0xffffffffu, lsB,  o);
        ls2B += __shfl_down_sync(0xffffffffu, ls2B, o);
    }
    if ((tid & 31) == 0) {
        rA[tid >> 5] = lsA;  rB[tid >> 5] = ls2A;
        rC[tid >> 5] = lsB;  rD[tid >> 5] = ls2B;
    }
    __syncthreads();
    // shifted copies (xs fully visible)
    for (int i = tid; i < PAD - 1; i += NTHR) { ys0[i] = xs0[i + 1]; ys1[i] = xs1[i + 1]; }
    if (tid == 0) {
        ys0[PAD - 1] = 0.0f; ys1[PAD - 1] = 0.0f;
        double SA = 0.0, S2A = 0.0, SB = 0.0, S2B = 0.0;
        #pragma unroll
        for (int w = 0; w < NWARP; w++) {
            SA += rA[w]; S2A += rB[w]; SB += rC[w]; S2B += rD[w];
        }
        double varA = (S2A - SA * SA / (double)T_LEN) / (double)(T_LEN - 1);
        double rsA  = (double)RR * (sqrt(varA) + 1e-8);
        s_thr0 = (float)(rsA * rsA);
        double varB = (S2B - SB * SB / (double)T_LEN) / (double)(T_LEN - 1);
        double rsB  = (double)RR * (sqrt(varB) + 1e-8);
        s_thr1 = (float)(rsB * rsB);
    }
    __syncthreads();
    const u64 NEG1 = 0xBF800000BF800000ull;

    // ---- counting: thread (P = tid&127, sg = tid>>7) does layers
    // l = B0+sg, B0+sg+3, ... < B1; split at signal boundary bnd. ----
    const int P  = tid & 127;
    const int sg = tid >> 7;           // warp-uniform, 0..2
    const int dA = 4 * P + 1;
    const int LA = NN - dA;
    const int dB = 1021 - 4 * P;
    const int LB = NN - dB;
    const int CA = (LA + 31) >> 5;
    const int bnd = min(B1, 33 * (sg0 + 1));
    const int l0  = B0 + sg;
    const int lB  = (l0 >= bnd) ? l0 : l0 + ((bnd - l0 + 2) / 3) * 3;

    unsigned int cmA = 0, cm1A = 0, cmB = 0, cm1B = 0;
    {
        const float Rs2 = s_thr0;
        const unsigned int nr = __float_as_uint(-Rs2);
        const u64 NRS2 = (u64)nr | ((u64)nr << 32);
        seg_process(xs0, ys0, l0, bnd, 33 * sg0, dA, dB, LA, LB, CA,
                    Rs2, NEG1, NRS2, cmA, cm1A);
    }
    {
        const float Rs2 = s_thr1;
        const unsigned int nr = __float_as_uint(-Rs2);
        const u64 NRS2 = (u64)nr | ((u64)nr << 32);
        seg_process(xs1, ys1, lB, B1, 33 * sg1, dA, dB, LA, LB, CA,
                    Rs2, NEG1, NRS2, cmB, cm1B);
    }

    // ---- reduce 4 count streams, atomically accumulate per signal ----
    #pragma unroll
    for (int o = 16; o > 0; o >>= 1) {
        cmA  += __shfl_down_sync(0xffffffffu, cmA,  o);
        cm1A += __shfl_down_sync(0xffffffffu, cm1A, o);
        cmB  += __shfl_down_sync(0xffffffffu, cmB,  o);
        cm1B += __shfl_down_sync(0xffffffffu, cm1B, o);
    }
    if ((tid & 31) == 0) {
        redc[0][tid >> 5] = cmA;  redc[1][tid >> 5] = cm1A;
        redc[2][tid >> 5] = cmB;  redc[3][tid >> 5] = cm1B;
    }
    __syncthreads();
    if (tid == 0) {
        unsigned int tA = 0, t1A = 0, tB = 0, t1B = 0;
        #pragma unroll
        for (int w = 0; w < NWARP; w++) {
            tA += redc[0][w]; t1A += redc[1][w];
            tB += redc[2][w]; t1B += redc[3][w];
        }
        atomicAdd(&g_cm[sg0],  tA);
        atomicAdd(&g_cm1[sg0], t1A);
        atomicAdd(&g_cm[sg1],  tB);
        atomicAdd(&g_cm1[sg1], t1B);
        __threadfence();
        s_last = (atomicAdd(&g_barrier, 1) == (unsigned int)(GRID - 1)) ? 1u : 0u;
    }
    __syncthreads();

    // ---- last block: entropies + MSE + counter reset ----
    if (s_last) {
        __threadfence();
        if (tid < 128) {
            unsigned int um  = __ldcg(&g_cm[tid]);
            unsigned int um1 = __ldcg(&g_cm1[tid]);
            // symmetric matrix + zero diagonal: matches = NN + 2*upper
            unsigned int matches_m  = (unsigned int)NN + 2u * um;
            unsigned int matches_m1 = (unsigned int)NN + 2u * um1;
            float ratio = (float)matches_m1 / (float)matches_m;
            ratio = fmaxf(ratio, 1e-30f);
            ent_sm[tid] = -logf(ratio);
            g_cm[tid]  = 0;
            g_cm1[tid] = 0;
        }
        __syncthreads();
        if (tid < 64) {
            float d = ent_sm[tid] - ent_sm[64 + tid];
            float v = d * d;
            #pragma unroll
            for (int o = 16; o > 0; o >>= 1)
                v += __shfl_down_sync(0xffffffffu, v, o);
            if ((tid & 31) == 0) part_sm[tid >> 5] = v;
        }
        __syncthreads();
        if (tid == 0) {
            out[0] = (part_sm[0] + part_sm[1]) * (1.0f / 64.0f);
            g_barrier = 0;
        }
    }
}

extern "C" void kernel_launch(void* const* d_in, const int* in_sizes, int n_in,
                              void* d_out, int out_size) {
    const float* pred = (const float*)d_in[0];
    const float* tgt  = (const float*)d_in[1];
    float* out = (float*)d_out;
    sampen_kernel<<<GRID, NTHR>>>(pred, tgt, out);
}